// round 17
// baseline (speedup 1.0000x reference)
#include <cuda_runtime.h>
#include <cuda_fp16.h>

#define N_USER 100000
#define N_ITEM 200000
#define N_NODE 300000
#define LATDIM 64
#define E_INTER 4000000
#define E_SOC   2000000

// All dense intermediates fp16.
// comb[k] = [ fp16(gate_k user rows) ; fp16(inter_{k} item rows) ]
__device__ __align__(256) __half g_comb [4][(size_t)N_NODE * LATDIM];
__device__ __align__(256) __half g_soch [4][(size_t)N_USER * LATDIM];
__device__ __align__(256) __half g_intUh[4][(size_t)N_USER * LATDIM];
__device__ __align__(256) __half g_fuh  [5][(size_t)N_USER * LATDIM];
__device__ __align__(256) __half g_it3  [(size_t)N_ITEM * LATDIM];

// CSR scratch. cnt arrays self-reset (zeroed by scan_final after use).
__device__ int  g_icnt[N_NODE];
__device__ int  g_icur[N_NODE];
__device__ int  g_iptr[N_NODE + 1];
__device__ __align__(16) int2 g_icv[E_INTER];
__device__ int  g_ibsum[256];

__device__ int  g_scnt[N_USER];
__device__ int  g_scur[N_USER];
__device__ int  g_sptr[N_USER + 1];
__device__ __align__(16) int2 g_scv[E_SOC];
__device__ int  g_sbsum[256];

// ---------------------------------------------------------------------------
// CSR build
// ---------------------------------------------------------------------------
__global__ void hist_rows(const int* __restrict__ rows, int E, int* __restrict__ cnt)
{
    int i = blockIdx.x * blockDim.x + threadIdx.x;
    if (i < E) atomicAdd(&cnt[rows[i]], 1);
}

__global__ void block_sum(const int* __restrict__ cnt, int N, int* __restrict__ bsum)
{
    __shared__ int sh[256];
    int base = blockIdx.x * 2048;
    int s = 0;
    for (int i = threadIdx.x; i < 2048; i += 256) {
        int idx = base + i;
        s += (idx < N) ? cnt[idx] : 0;
    }
    sh[threadIdx.x] = s;
    __syncthreads();
    for (int o = 128; o; o >>= 1) {
        if (threadIdx.x < o) sh[threadIdx.x] += sh[threadIdx.x + o];
        __syncthreads();
    }
    if (threadIdx.x == 0) bsum[blockIdx.x] = sh[0];
}

__global__ void scan_final(int* __restrict__ cnt, int N,
                           const int* __restrict__ bsum, int NB,
                           int* __restrict__ ptr, int* __restrict__ cur, int E)
{
    __shared__ int shb[256];
    __shared__ int sh[256];
    int t = threadIdx.x;

    shb[t] = (t < NB) ? bsum[t] : 0;
    __syncthreads();
    for (int o = 1; o < 256; o <<= 1) {
        int y = (t >= o) ? shb[t - o] : 0;
        __syncthreads();
        shb[t] += y;
        __syncthreads();
    }
    int block_off = (blockIdx.x == 0) ? 0 : shb[blockIdx.x - 1];

    int base = blockIdx.x * 2048 + t * 8;
    int loc[8];
    int s = 0;
    #pragma unroll
    for (int j = 0; j < 8; j++) {
        int idx = base + j;
        loc[j] = (idx < N) ? cnt[idx] : 0;
        if (idx < N) cnt[idx] = 0;           // self-reset for next call
        s += loc[j];
    }
    sh[t] = s;
    __syncthreads();
    for (int o = 1; o < 256; o <<= 1) {
        int y = (t >= o) ? sh[t - o] : 0;
        __syncthreads();
        sh[t] += y;
        __syncthreads();
    }
    int run = block_off + sh[t] - s;
    #pragma unroll
    for (int j = 0; j < 8; j++) {
        int idx = base + j;
        if (idx < N) { ptr[idx] = run; cur[idx] = run; run += loc[j]; }
    }
    if (blockIdx.x == 0 && t == 0) ptr[N] = E;
}

__global__ void scatter_edges(const int* __restrict__ rows, const int* __restrict__ cols,
                              const float* __restrict__ vals, int E,
                              int* __restrict__ cur, int2* __restrict__ cv)
{
    int i = blockIdx.x * blockDim.x + threadIdx.x;
    if (i >= E) return;
    int p = atomicAdd(&cur[rows[i]], 1);
    cv[p] = make_int2(cols[i], __float_as_int(vals[i]));
}

__global__ void scatter_conv(const int* __restrict__ rows, const int* __restrict__ cols,
                             const float* __restrict__ vals, int E,
                             int* __restrict__ cur, int2* __restrict__ cv,
                             const float2* __restrict__ iE2, __half2* __restrict__ dst2,
                             int nI2)
{
    int i = blockIdx.x * blockDim.x + threadIdx.x;
    if (i < E) {
        int p = atomicAdd(&cur[rows[i]], 1);
        cv[p] = make_int2(cols[i], __float_as_int(vals[i]));
    }
    if (i < nI2) dst2[i] = __float22half2_rn(iE2[i]);
}

// ---------------------------------------------------------------------------
// CSR SpMM: 16 lanes/row, pair-lane split; row range [r0, r1).
//   Software-pipelined edge stream: next iteration's cv values are loaded
//   while the current iteration's gathers/FMAs run. fp32 accumulate;
//   single fp16 store per row (pair 1). Tail ladder 4 -> 2 -> 1.
// ---------------------------------------------------------------------------
__device__ __forceinline__ void acc8(float* acc, uint4 w, float v)
{
    float2 f0 = __half22float2(*reinterpret_cast<__half2*>(&w.x));
    float2 f1 = __half22float2(*reinterpret_cast<__half2*>(&w.y));
    float2 f2 = __half22float2(*reinterpret_cast<__half2*>(&w.z));
    float2 f3 = __half22float2(*reinterpret_cast<__half2*>(&w.w));
    acc[0] += v * f0.x; acc[1] += v * f0.y;
    acc[2] += v * f1.x; acc[3] += v * f1.y;
    acc[4] += v * f2.x; acc[5] += v * f2.y;
    acc[6] += v * f3.x; acc[7] += v * f3.y;
}

__device__ __forceinline__ void gather4_acc(const __half* __restrict__ src, int q,
                                            int2 a0, int2 a1, int2 a2, int2 a3,
                                            float* acc)
{
    uint4 w0 = __ldg((const uint4*)(src + (size_t)a0.x * LATDIM) + q);
    uint4 w1 = __ldg((const uint4*)(src + (size_t)a1.x * LATDIM) + q);
    uint4 w2 = __ldg((const uint4*)(src + (size_t)a2.x * LATDIM) + q);
    uint4 w3 = __ldg((const uint4*)(src + (size_t)a3.x * LATDIM) + q);
    acc8(acc, w0, __int_as_float(a0.y));
    acc8(acc, w1, __int_as_float(a1.y));
    acc8(acc, w2, __int_as_float(a2.y));
    acc8(acc, w3, __int_as_float(a3.y));
}

__global__ void __launch_bounds__(256) spmm_f16(
    const int* __restrict__ ptr, const int2* __restrict__ cv,
    const __half* __restrict__ src,
    __half* __restrict__ dsth, int hoff, int r0, int r1)
{
    int t = blockIdx.x * blockDim.x + threadIdx.x;
    int row = r0 + (t >> 4);
    int lane = threadIdx.x & 15;
    int pair = lane >> 3;
    int q    = lane & 7;
    bool valid = row < r1;

    int s = 0, e = 0;
    if (valid) { s = __ldg(ptr + row); e = __ldg(ptr + row + 1); }

    float acc[8] = {0.f, 0.f, 0.f, 0.f, 0.f, 0.f, 0.f, 0.f};
    int i = s;
    if (i + 8 <= e) {
        // pipeline prologue: load first 8-edge packet
        int2 a0 = __ldg(cv + i     + pair);
        int2 a1 = __ldg(cv + i + 2 + pair);
        int2 a2 = __ldg(cv + i + 4 + pair);
        int2 a3 = __ldg(cv + i + 6 + pair);
        i += 8;
        for (; i + 8 <= e; i += 8) {
            // preload next packet, then consume current
            int2 b0 = __ldg(cv + i     + pair);
            int2 b1 = __ldg(cv + i + 2 + pair);
            int2 b2 = __ldg(cv + i + 4 + pair);
            int2 b3 = __ldg(cv + i + 6 + pair);
            gather4_acc(src, q, a0, a1, a2, a3, acc);
            a0 = b0; a1 = b1; a2 = b2; a3 = b3;
        }
        gather4_acc(src, q, a0, a1, a2, a3, acc);   // drain
    }
    if (i + 4 <= e) {
        int2 a0 = __ldg(cv + i     + pair);
        int2 a1 = __ldg(cv + i + 2 + pair);
        uint4 w0 = __ldg((const uint4*)(src + (size_t)a0.x * LATDIM) + q);
        uint4 w1 = __ldg((const uint4*)(src + (size_t)a1.x * LATDIM) + q);
        acc8(acc, w0, __int_as_float(a0.y));
        acc8(acc, w1, __int_as_float(a1.y));
        i += 4;
    }
    if (i + 2 <= e) {
        int2 a = __ldg(cv + i + pair);
        uint4 w = __ldg((const uint4*)(src + (size_t)a.x * LATDIM) + q);
        acc8(acc, w, __int_as_float(a.y));
        i += 2;
    }
    if (i < e && pair == 0) {
        int2 a = __ldg(cv + i);
        uint4 w = __ldg((const uint4*)(src + (size_t)a.x * LATDIM) + q);
        acc8(acc, w, __int_as_float(a.y));
    }

    #pragma unroll
    for (int j = 0; j < 8; j++)
        acc[j] += __shfl_xor_sync(0xffffffffu, acc[j], 8);

    if (valid && pair == 1) {
        __half2 h0 = __floats2half2_rn(acc[0], acc[1]);
        __half2 h1 = __floats2half2_rn(acc[2], acc[3]);
        __half2 h2 = __floats2half2_rn(acc[4], acc[5]);
        __half2 h3 = __floats2half2_rn(acc[6], acc[7]);
        uint4 pk;
        pk.x = *reinterpret_cast<unsigned*>(&h0);
        pk.y = *reinterpret_cast<unsigned*>(&h1);
        pk.z = *reinterpret_cast<unsigned*>(&h2);
        pk.w = *reinterpret_cast<unsigned*>(&h3);
        ((uint4*)(dsth + (size_t)(row - hoff) * LATDIM))[q] = pk;
    }
}

// fp32-source variant (soc layer 0 only, gathering uE); fp16 out; pipelined
__global__ void __launch_bounds__(256) spmm_f32src(
    const int* __restrict__ ptr, const int2* __restrict__ cv,
    const float* __restrict__ src,
    __half* __restrict__ dsth, int nrows)
{
    int hw = (blockIdx.x * blockDim.x + threadIdx.x) >> 4;
    int q  = threadIdx.x & 15;
    if (hw >= nrows) return;
    int s = __ldg(ptr + hw);
    int e = __ldg(ptr + hw + 1);
    float4 acc = make_float4(0.f, 0.f, 0.f, 0.f);
    int i = s;
    if (i + 4 <= e) {
        int2 a0 = __ldg(cv + i),     a1 = __ldg(cv + i + 1);
        int2 a2 = __ldg(cv + i + 2), a3 = __ldg(cv + i + 3);
        i += 4;
        for (; i + 4 <= e; i += 4) {
            int2 b0 = __ldg(cv + i),     b1 = __ldg(cv + i + 1);
            int2 b2 = __ldg(cv + i + 2), b3 = __ldg(cv + i + 3);
            float4 x0 = __ldg((const float4*)(src + (size_t)a0.x * LATDIM) + q);
            float4 x1 = __ldg((const float4*)(src + (size_t)a1.x * LATDIM) + q);
            float4 x2 = __ldg((const float4*)(src + (size_t)a2.x * LATDIM) + q);
            float4 x3 = __ldg((const float4*)(src + (size_t)a3.x * LATDIM) + q);
            float v0 = __int_as_float(a0.y), v1 = __int_as_float(a1.y);
            float v2 = __int_as_float(a2.y), v3 = __int_as_float(a3.y);
            acc.x += v0 * x0.x; acc.y += v0 * x0.y; acc.z += v0 * x0.z; acc.w += v0 * x0.w;
            acc.x += v1 * x1.x; acc.y += v1 * x1.y; acc.z += v1 * x1.z; acc.w += v1 * x1.w;
            acc.x += v2 * x2.x; acc.y += v2 * x2.y; acc.z += v2 * x2.z; acc.w += v2 * x2.w;
            acc.x += v3 * x3.x; acc.y += v3 * x3.y; acc.z += v3 * x3.z; acc.w += v3 * x3.w;
            a0 = b0; a1 = b1; a2 = b2; a3 = b3;
        }
        float4 x0 = __ldg((const float4*)(src + (size_t)a0.x * LATDIM) + q);
        float4 x1 = __ldg((const float4*)(src + (size_t)a1.x * LATDIM) + q);
        float4 x2 = __ldg((const float4*)(src + (size_t)a2.x * LATDIM) + q);
        float4 x3 = __ldg((const float4*)(src + (size_t)a3.x * LATDIM) + q);
        float v0 = __int_as_float(a0.y), v1 = __int_as_float(a1.y);
        float v2 = __int_as_float(a2.y), v3 = __int_as_float(a3.y);
        acc.x += v0 * x0.x; acc.y += v0 * x0.y; acc.z += v0 * x0.z; acc.w += v0 * x0.w;
        acc.x += v1 * x1.x; acc.y += v1 * x1.y; acc.z += v1 * x1.z; acc.w += v1 * x1.w;
        acc.x += v2 * x2.x; acc.y += v2 * x2.y; acc.z += v2 * x2.z; acc.w += v2 * x2.w;
        acc.x += v3 * x3.x; acc.y += v3 * x3.y; acc.z += v3 * x3.z; acc.w += v3 * x3.w;
    }
    if (i + 2 <= e) {
        int2 a0 = __ldg(cv + i), a1 = __ldg(cv + i + 1);
        float4 x0 = __ldg((const float4*)(src + (size_t)a0.x * LATDIM) + q);
        float4 x1 = __ldg((const float4*)(src + (size_t)a1.x * LATDIM) + q);
        float v0 = __int_as_float(a0.y), v1 = __int_as_float(a1.y);
        acc.x += v0 * x0.x; acc.y += v0 * x0.y; acc.z += v0 * x0.z; acc.w += v0 * x0.w;
        acc.x += v1 * x1.x; acc.y += v1 * x1.y; acc.z += v1 * x1.z; acc.w += v1 * x1.w;
        i += 2;
    }
    if (i < e) {
        int2 a = __ldg(cv + i);
        float4 x = __ldg((const float4*)(src + (size_t)a.x * LATDIM) + q);
        float v = __int_as_float(a.y);
        acc.x += v * x.x; acc.y += v * x.y; acc.z += v * x.z; acc.w += v * x.w;
    }
    __half2 h0 = __floats2half2_rn(acc.x, acc.y);
    __half2 h1 = __floats2half2_rn(acc.z, acc.w);
    uint2 pk;
    pk.x = *reinterpret_cast<unsigned*>(&h0);
    pk.y = *reinterpret_cast<unsigned*>(&h1);
    ((uint2*)(dsth + (size_t)hw * LATDIM))[q] = pk;
}

// ---------------------------------------------------------------------------
// Gates: fp32 math; fp16 outputs.
// ---------------------------------------------------------------------------
__device__ __forceinline__ void gate_core(float2 za, float2 ha,
                                          const float* __restrict__ Wg,
                                          const float* __restrict__ bg,
                                          int lane, float2& o2)
{
    int d = 2 * lane;
    float p0 = za.x * Wg[d]       + za.y * Wg[d + 1]
             + ha.x * Wg[64 + d]  + ha.y * Wg[64 + d + 1];
    float p1 = za.x * Wg[128 + d]      + za.y * Wg[128 + d + 1]
             + ha.x * Wg[128 + 64 + d] + ha.y * Wg[128 + 64 + d + 1];
    #pragma unroll
    for (int o = 16; o; o >>= 1) {
        p0 += __shfl_xor_sync(0xffffffffu, p0, o);
        p1 += __shfl_xor_sync(0xffffffffu, p1, o);
    }
    float l0 = p0 + bg[0];
    float l1 = p1 + bg[1];
    l0 = l0 > 0.f ? l0 : 0.01f * l0;
    l1 = l1 > 0.f ? l1 : 0.01f * l1;
    float mx = fmaxf(l0, l1);
    float e0 = __expf(l0 - mx), e1 = __expf(l1 - mx);
    float inv = 1.f / (e0 + e1);
    float m0 = e0 * inv, m1 = e1 * inv;
    o2 = make_float2(za.x * m0 + ha.x * m1, za.y * m0 + ha.y * m1);
}

__global__ void gate_fuse_f32(const float* __restrict__ uu, const float* __restrict__ hi,
                              const float* __restrict__ Wg, const float* __restrict__ bg,
                              __half* __restrict__ outh1, __half* __restrict__ outh2)
{
    int gt = blockIdx.x * blockDim.x + threadIdx.x;
    int u = gt >> 5;
    int lane = threadIdx.x & 31;
    if (u >= N_USER) return;
    float2 za = ((const float2*)(uu + (size_t)u * LATDIM))[lane];
    float2 ha = ((const float2*)(hi + (size_t)u * LATDIM))[lane];
    float2 o2;
    gate_core(za, ha, Wg, bg, lane, o2);
    __half2 oh = __float22half2_rn(o2);
    ((__half2*)(outh1 + (size_t)u * LATDIM))[lane] = oh;
    if (outh2 != nullptr)
        ((__half2*)(outh2 + (size_t)u * LATDIM))[lane] = oh;
}

__global__ void gate_fuse_f16(const __half* __restrict__ uu, const __half* __restrict__ hi,
                              const float* __restrict__ Wg, const float* __restrict__ bg,
                              __half* __restrict__ outh1, __half* __restrict__ outh2)
{
    int gt = blockIdx.x * blockDim.x + threadIdx.x;
    int u = gt >> 5;
    int lane = threadIdx.x & 31;
    if (u >= N_USER) return;
    float2 za = __half22float2(((const __half2*)(uu + (size_t)u * LATDIM))[lane]);
    float2 ha = __half22float2(((const __half2*)(hi + (size_t)u * LATDIM))[lane]);
    float2 o2;
    gate_core(za, ha, Wg, bg, lane, o2);
    __half2 oh = __float22half2_rn(o2);
    ((__half2*)(outh1 + (size_t)u * LATDIM))[lane] = oh;
    if (outh2 != nullptr)
        ((__half2*)(outh2 + (size_t)u * LATDIM))[lane] = oh;
}

// ---------------------------------------------------------------------------
// 5-way attention readouts.
// ---------------------------------------------------------------------------
__device__ __forceinline__ void attn_core(float2* f, const float* sW, const float* sb,
                                          int lane, float2& o2)
{
    int d = 2 * lane;
    float p[5];
    #pragma unroll
    for (int j = 0; j < 5; j++) {
        float acc = 0.f;
        #pragma unroll
        for (int k = 0; k < 5; k++) {
            acc += f[k].x * sW[j * 320 + k * 64 + d];
            acc += f[k].y * sW[j * 320 + k * 64 + d + 1];
        }
        p[j] = acc;
    }
    #pragma unroll
    for (int j = 0; j < 5; j++)
        #pragma unroll
        for (int o = 16; o; o >>= 1)
            p[j] += __shfl_xor_sync(0xffffffffu, p[j], o);

    float mx = -1e30f;
    #pragma unroll
    for (int j = 0; j < 5; j++) {
        float l = p[j] + sb[j];
        l = l > 0.f ? l : 0.01f * l;
        p[j] = l;
        mx = fmaxf(mx, l);
    }
    float se = 0.f;
    #pragma unroll
    for (int j = 0; j < 5; j++) { p[j] = __expf(p[j] - mx); se += p[j]; }
    float inv = 1.f / se;

    o2 = make_float2(0.f, 0.f);
    #pragma unroll
    for (int k = 0; k < 5; k++) {
        float w = p[k] * inv;
        o2.x += w * f[k].x;
        o2.y += w * f[k].y;
    }
}

__global__ void attn5_allh(const __half* __restrict__ h0, const __half* __restrict__ h1,
                           const __half* __restrict__ h2, const __half* __restrict__ h3,
                           const __half* __restrict__ h4,
                           const float* __restrict__ W, const float* __restrict__ b,
                           float* __restrict__ out, int N)
{
    __shared__ float sW[5 * 320];
    __shared__ float sb[5];
    for (int i = threadIdx.x; i < 5 * 320; i += blockDim.x) sW[i] = W[i];
    if (threadIdx.x < 5) sb[threadIdx.x] = b[threadIdx.x];
    __syncthreads();

    int gt = blockIdx.x * blockDim.x + threadIdx.x;
    int u = gt >> 5;
    int lane = threadIdx.x & 31;
    if (u >= N) return;

    const __half* hp[5] = {h0, h1, h2, h3, h4};
    float2 f[5];
    #pragma unroll
    for (int k = 0; k < 5; k++)
        f[k] = __half22float2(((const __half2*)(hp[k] + (size_t)u * LATDIM))[lane]);

    float2 o2;
    attn_core(f, sW, sb, lane, o2);
    ((float2*)(out + (size_t)u * LATDIM))[lane] = o2;
}

__global__ void attn5h(const float* __restrict__ f0,
                       const __half* __restrict__ h1, const __half* __restrict__ h2,
                       const __half* __restrict__ h3, const __half* __restrict__ h4,
                       const float* __restrict__ W, const float* __restrict__ b,
                       float* __restrict__ out, int N)
{
    __shared__ float sW[5 * 320];
    __shared__ float sb[5];
    for (int i = threadIdx.x; i < 5 * 320; i += blockDim.x) sW[i] = W[i];
    if (threadIdx.x < 5) sb[threadIdx.x] = b[threadIdx.x];
    __syncthreads();

    int gt = blockIdx.x * blockDim.x + threadIdx.x;
    int u = gt >> 5;
    int lane = threadIdx.x & 31;
    if (u >= N) return;

    float2 f[5];
    f[0] = ((const float2*)(f0 + (size_t)u * LATDIM))[lane];
    const __half* hp[4] = {h1, h2, h3, h4};
    #pragma unroll
    for (int k = 0; k < 4; k++)
        f[k + 1] = __half22float2(((const __half2*)(hp[k] + (size_t)u * LATDIM))[lane]);

    float2 o2;
    attn_core(f, sW, sb, lane, o2);
    ((float2*)(out + (size_t)u * LATDIM))[lane] = o2;
}

// ---------------------------------------------------------------------------

extern "C" void kernel_launch(void* const* d_in, const int* in_sizes, int n_in,
                              void* d_out, int out_size)
{
    const float* uE  = (const float*)d_in[0];
    const float* iE  = (const float*)d_in[1];
    const float* Wg  = (const float*)d_in[2];
    const float* bg  = (const float*)d_in[3];
    const float* WL1 = (const float*)d_in[4];
    const float* bL1 = (const float*)d_in[5];
    const float* WL2 = (const float*)d_in[6];
    const float* bL2 = (const float*)d_in[7];
    const int*   ir  = (const int*)d_in[8];
    const int*   ic  = (const int*)d_in[9];
    const float* iv  = (const float*)d_in[10];
    const int*   sr  = (const int*)d_in[11];
    const int*   sc  = (const int*)d_in[12];
    const float* sv  = (const float*)d_in[13];
    float* out = (float*)d_out;

    __half *combB, *socH, *intUh, *fuH, *it3;
    cudaGetSymbolAddress((void**)&combB, g_comb);
    cudaGetSymbolAddress((void**)&socH,  g_soch);
    cudaGetSymbolAddress((void**)&intUh, g_intUh);
    cudaGetSymbolAddress((void**)&fuH,   g_fuh);
    cudaGetSymbolAddress((void**)&it3,   g_it3);

    int *icnt, *icur, *iptr, *ibs, *scnt, *scur, *sptr, *sbs;
    int2 *icv, *scv;
    cudaGetSymbolAddress((void**)&icnt, g_icnt);
    cudaGetSymbolAddress((void**)&icur, g_icur);
    cudaGetSymbolAddress((void**)&iptr, g_iptr);
    cudaGetSymbolAddress((void**)&icv,  g_icv);
    cudaGetSymbolAddress((void**)&ibs,  g_ibsum);
    cudaGetSymbolAddress((void**)&scnt, g_scnt);
    cudaGetSymbolAddress((void**)&scur, g_scur);
    cudaGetSymbolAddress((void**)&sptr, g_sptr);
    cudaGetSymbolAddress((void**)&scv,  g_scv);
    cudaGetSymbolAddress((void**)&sbs,  g_sbsum);

    const size_t USZ = (size_t)N_USER * LATDIM;
    const size_t NSZ = (size_t)N_NODE * LATDIM;
    const int NB_I = (N_NODE + 2047) / 2048;   // 147
    const int NB_S = (N_USER + 2047) / 2048;   // 49
    const int nI2 = N_ITEM * LATDIM / 2;       // 6.4M half2

    const int GRID_U = (N_USER * 16 + 255) / 256;
    const int GRID_I = (N_ITEM * 16 + 255) / 256;

    // --- streams & events (s3 = item chain + inter CSR build, high priority) ---
    int prLow, prHigh;
    cudaDeviceGetStreamPriorityRange(&prLow, &prHigh);
    cudaStream_t s2, s3;
    cudaStreamCreateWithFlags(&s2, cudaStreamNonBlocking);
    cudaStreamCreateWithPriority(&s3, cudaStreamNonBlocking, prHigh);
    cudaEvent_t evFork, evSoc[4], evGate[4], evItem[4], evBuildI, evAttnI;
    cudaEventCreateWithFlags(&evFork, cudaEventDisableTiming);
    cudaEventCreateWithFlags(&evBuildI, cudaEventDisableTiming);
    cudaEventCreateWithFlags(&evAttnI, cudaEventDisableTiming);
    for (int k = 0; k < 4; k++) {
        cudaEventCreateWithFlags(&evSoc[k],  cudaEventDisableTiming);
        cudaEventCreateWithFlags(&evGate[k], cudaEventDisableTiming);
        cudaEventCreateWithFlags(&evItem[k], cudaEventDisableTiming);
    }

    cudaEventRecord(evFork, 0);
    cudaStreamWaitEvent(s2, evFork, 0);
    cudaStreamWaitEvent(s3, evFork, 0);

    // === s2: soc CSR build + soc chain (layers 1..4) ===
    hist_rows<<<(E_SOC + 255) / 256, 256, 0, s2>>>(sr, E_SOC, scnt);
    block_sum<<<NB_S, 256, 0, s2>>>(scnt, N_USER, sbs);
    scan_final<<<NB_S, 256, 0, s2>>>(scnt, N_USER, sbs, NB_S, sptr, scur, E_SOC);
    scatter_edges<<<(E_SOC + 255) / 256, 256, 0, s2>>>(sr, sc, sv, E_SOC, scur, scv);

    spmm_f32src<<<GRID_U, 256, 0, s2>>>(sptr, scv, uE, socH, N_USER);
    cudaEventRecord(evSoc[0], s2);
    for (int k = 1; k < 4; k++) {
        spmm_f16<<<GRID_U, 256, 0, s2>>>(
            sptr, scv, socH + (size_t)(k - 1) * USZ,
            socH + (size_t)k * USZ, 0, 0, N_USER);
        cudaEventRecord(evSoc[k], s2);
    }

    // === s3: inter CSR build (+ iE fp16 conv), concurrent with gate0 ===
    hist_rows<<<(E_INTER + 255) / 256, 256, 0, s3>>>(ir, E_INTER, icnt);
    block_sum<<<NB_I, 256, 0, s3>>>(icnt, N_NODE, ibs);
    scan_final<<<NB_I, 256, 0, s3>>>(icnt, N_NODE, ibs, NB_I, iptr, icur, E_INTER);
    {
        int tot = (E_INTER > nI2) ? E_INTER : nI2;
        scatter_conv<<<(tot + 255) / 256, 256, 0, s3>>>(ir, ic, iv, E_INTER, icur, icv,
                                                        (const float2*)iE,
                                                        (__half2*)(combB + USZ), nI2);
    }
    cudaEventRecord(evBuildI, s3);

    // === main: gate0 (uE only) ===
    gate_fuse_f32<<<(N_USER * 32 + 255) / 256, 256>>>(
        uE, uE, Wg, bg, combB, fuH);                   // comb[0] user + fused[0]
    cudaEventRecord(evGate[0], 0);

    // === layers 0..3: user-spmm on main, item-spmm on s3 ===
    for (int k = 0; k < 4; k++) {
        __half* combk = combB + (size_t)k * NSZ;

        // item rows -> comb[k+1] item region (k<3) or it3 (k=3), on s3
        cudaStreamWaitEvent(s3, evGate[k], 0);   // comb[k] user region ready
        __half* dsthI = (k < 3) ? combB + (size_t)(k + 1) * NSZ + USZ : it3;
        spmm_f16<<<GRID_I, 256, 0, s3>>>(
            iptr, icv, combk, dsthI, N_USER, N_USER, N_NODE);
        cudaEventRecord(evItem[k], s3);

        // user rows -> intUh[k] (main)
        if (k == 0) cudaStreamWaitEvent(0, evBuildI, 0);   // CSR + comb[0] items
        else        cudaStreamWaitEvent(0, evItem[k - 1], 0);
        spmm_f16<<<GRID_U, 256>>>(
            iptr, icv, combk, intUh + (size_t)k * USZ, 0, 0, N_USER);

        // gate_{k+1}: socH[k] + intUh[k] -> comb[k+1] user (k<3) + fused[k+1]
        cudaStreamWaitEvent(0, evSoc[k], 0);
        gate_fuse_f16<<<(N_USER * 32 + 255) / 256, 256>>>(
            socH + (size_t)k * USZ, intUh + (size_t)k * USZ,
            Wg + (k + 1) * 256, bg + (k + 1) * 2,
            fuH + (size_t)(k + 1) * USZ,
            (k < 3) ? combB + (size_t)(k + 1) * NSZ : nullptr);
        if (k < 3) cudaEventRecord(evGate[k + 1], 0);
    }

    // --- attention readouts: item side on s3, user on main ---
    attn5h<<<(N_ITEM * 32 + 255) / 256, 256, 0, s3>>>(
        iE,
        combB + 1 * NSZ + USZ, combB + 2 * NSZ + USZ, combB + 3 * NSZ + USZ, it3,
        WL2, bL2, out + USZ, N_ITEM);
    cudaEventRecord(evAttnI, s3);

    attn5_allh<<<(N_USER * 32 + 255) / 256, 256>>>(
        fuH, fuH + USZ, fuH + 2 * USZ, fuH + 3 * USZ, fuH + 4 * USZ,
        WL1, bL1, out, N_USER);

    // join s3 back into main
    cudaStreamWaitEvent(0, evAttnI, 0);

    // --- cleanup ---
    cudaEventDestroy(evFork);
    cudaEventDestroy(evBuildI);
    cudaEventDestroy(evAttnI);
    for (int k = 0; k < 4; k++) {
        cudaEventDestroy(evSoc[k]);
        cudaEventDestroy(evGate[k]);
        cudaEventDestroy(evItem[k]);
    }
    cudaStreamDestroy(s2);
    cudaStreamDestroy(s3);
}